// round 1
// baseline (speedup 1.0000x reference)
#include <cuda_runtime.h>
#include <math.h>

// Problem constants
#define B   256
#define Hd  1024
#define L   400
#define V   50257

// Output layout: logp [B*V], h_new [B*H], attn_weights [B*L]
#define OUT_LOGP 0
#define OUT_H    ((long)B * V)
#define OUT_AW   ((long)B * V + (long)B * Hd)

// ---------------- scratch (device globals; no allocation allowed) ----------
__device__ float g_xh[B * 2 * Hd];        // concat(x, h)
__device__ float g_scores[B * L];         // attention logits
__device__ float g_attn[B * Hd];          // attn_applied
__device__ float g_xa[B * 2 * Hd];        // concat(x, attn_applied)
__device__ float g_o[B * Hd];             // relu(combine)
__device__ float g_gi[B * 3 * Hd];        // o @ Wih^T + bih
__device__ float g_gh[B * 3 * Hd];        // h @ Whh^T + bhh
__device__ float g_logits[(long)B * V];   // pre-softmax logits

// ---------------- GEMM: C[M,N] = A[M,K] @ W[N,K]^T (+bias, +relu) ----------
#define BM 64
#define BN 64
#define BK 16

__global__ void gemm_tn(const float* __restrict__ A, const float* __restrict__ W,
                        const float* __restrict__ bias, float* __restrict__ C,
                        int M, int N, int K, int relu)
{
    __shared__ float As[BK][BM];
    __shared__ float Ws[BK][BN];
    int tid = threadIdx.x;
    int tx = tid & 15, ty = tid >> 4;
    int m0 = blockIdx.y * BM, n0 = blockIdx.x * BN;
    int lrow = tid >> 2;          // 0..63
    int lk4  = (tid & 3) * 4;     // 0,4,8,12
    float acc[4][4] = {};

    for (int k0 = 0; k0 < K; k0 += BK) {
        // A tile (M always multiple of 64 here, K multiple of 16, 16B aligned)
        float4 av = *(const float4*)&A[(long)(m0 + lrow) * K + k0 + lk4];
        As[lk4 + 0][lrow] = av.x; As[lk4 + 1][lrow] = av.y;
        As[lk4 + 2][lrow] = av.z; As[lk4 + 3][lrow] = av.w;
        // W tile, bounds-checked in N
        int n = n0 + lrow;
        float4 wv = make_float4(0.f, 0.f, 0.f, 0.f);
        if (n < N) wv = *(const float4*)&W[(long)n * K + k0 + lk4];
        Ws[lk4 + 0][lrow] = wv.x; Ws[lk4 + 1][lrow] = wv.y;
        Ws[lk4 + 2][lrow] = wv.z; Ws[lk4 + 3][lrow] = wv.w;
        __syncthreads();
        #pragma unroll
        for (int k = 0; k < BK; k++) {
            float4 a4 = *(const float4*)&As[k][ty * 4];
            float4 b4 = *(const float4*)&Ws[k][tx * 4];
            float aa[4] = {a4.x, a4.y, a4.z, a4.w};
            float bb[4] = {b4.x, b4.y, b4.z, b4.w};
            #pragma unroll
            for (int i = 0; i < 4; i++)
                #pragma unroll
                for (int j = 0; j < 4; j++)
                    acc[i][j] = fmaf(aa[i], bb[j], acc[i][j]);
        }
        __syncthreads();
    }
    #pragma unroll
    for (int i = 0; i < 4; i++) {
        int m = m0 + ty * 4 + i;
        #pragma unroll
        for (int j = 0; j < 4; j++) {
            int n = n0 + tx * 4 + j;
            if (n < N) {
                float v = acc[i][j] + (bias ? bias[n] : 0.f);
                if (relu) v = fmaxf(v, 0.f);
                C[(long)m * N + n] = v;
            }
        }
    }
}

// ---------------- GEMM: C[M,N] = A[M,K] @ Bm[K,N] (row-major B) ------------
__global__ void gemm_nn(const float* __restrict__ A, const float* __restrict__ Bm,
                        float* __restrict__ C, int M, int N, int K)
{
    __shared__ float As[BK][BM];
    __shared__ float Bs[BK][BN];
    int tid = threadIdx.x;
    int tx = tid & 15, ty = tid >> 4;
    int m0 = blockIdx.y * BM, n0 = blockIdx.x * BN;
    int lrow = tid >> 2;
    int lk4  = (tid & 3) * 4;
    int bkk = tid >> 4;           // 0..15
    int bn4 = (tid & 15) * 4;     // 0..60
    float acc[4][4] = {};

    for (int k0 = 0; k0 < K; k0 += BK) {
        float4 av = *(const float4*)&A[(long)(m0 + lrow) * K + k0 + lk4];
        As[lk4 + 0][lrow] = av.x; As[lk4 + 1][lrow] = av.y;
        As[lk4 + 2][lrow] = av.z; As[lk4 + 3][lrow] = av.w;
        int n = n0 + bn4;
        float4 bv = make_float4(0.f, 0.f, 0.f, 0.f);
        if (n < N) bv = *(const float4*)&Bm[(long)(k0 + bkk) * N + n];
        Bs[bkk][bn4 + 0] = bv.x; Bs[bkk][bn4 + 1] = bv.y;
        Bs[bkk][bn4 + 2] = bv.z; Bs[bkk][bn4 + 3] = bv.w;
        __syncthreads();
        #pragma unroll
        for (int k = 0; k < BK; k++) {
            float4 a4 = *(const float4*)&As[k][ty * 4];
            float4 b4 = *(const float4*)&Bs[k][tx * 4];
            float aa[4] = {a4.x, a4.y, a4.z, a4.w};
            float bb[4] = {b4.x, b4.y, b4.z, b4.w};
            #pragma unroll
            for (int i = 0; i < 4; i++)
                #pragma unroll
                for (int j = 0; j < 4; j++)
                    acc[i][j] = fmaf(aa[i], bb[j], acc[i][j]);
        }
        __syncthreads();
    }
    #pragma unroll
    for (int i = 0; i < 4; i++) {
        int m = m0 + ty * 4 + i;
        #pragma unroll
        for (int j = 0; j < 4; j++) {
            int n = n0 + tx * 4 + j;
            if (n < N) C[(long)m * N + n] = acc[i][j];
        }
    }
}

// ---------------- concat along feature dim ---------------------------------
__global__ void concat2(const float* __restrict__ a, const float* __restrict__ b,
                        float* __restrict__ out, int rows, int h)
{
    int idx = blockIdx.x * blockDim.x + threadIdx.x;
    int total = rows * 2 * h;
    if (idx >= total) return;
    int r = idx / (2 * h);
    int c = idx - r * 2 * h;
    out[idx] = (c < h) ? a[r * h + c] : b[r * h + (c - h)];
}

// ---------------- softmax over rows of length n (n small, L=400) -----------
__global__ void softmax_rows(const float* __restrict__ in, float* __restrict__ out, int n)
{
    int row = blockIdx.x;
    const float* x = in + (long)row * n;
    float* y = out + (long)row * n;
    __shared__ float red[4];
    int tid = threadIdx.x;          // 128 threads
    int wid = tid >> 5, lid = tid & 31;

    float m = -1e30f;
    for (int i = tid; i < n; i += 128) m = fmaxf(m, x[i]);
    #pragma unroll
    for (int o = 16; o > 0; o >>= 1) m = fmaxf(m, __shfl_xor_sync(0xffffffff, m, o));
    if (lid == 0) red[wid] = m;
    __syncthreads();
    m = fmaxf(fmaxf(red[0], red[1]), fmaxf(red[2], red[3]));

    float s = 0.f;
    for (int i = tid; i < n; i += 128) s += __expf(x[i] - m);
    #pragma unroll
    for (int o = 16; o > 0; o >>= 1) s += __shfl_xor_sync(0xffffffff, s, o);
    __syncthreads();
    if (lid == 0) red[wid] = s;
    __syncthreads();
    s = red[0] + red[1] + red[2] + red[3];
    float inv = 1.f / s;
    for (int i = tid; i < n; i += 128) y[i] = __expf(x[i] - m) * inv;
}

// ---------------- log_softmax over rows of length V -------------------------
__global__ void logsoftmax_rows(const float* __restrict__ in, float* __restrict__ out, int n)
{
    int row = blockIdx.x;
    const float* x = in + (long)row * n;
    float* y = out + (long)row * n;
    __shared__ float red[32];
    int tid = threadIdx.x;          // 1024 threads
    int wid = tid >> 5, lid = tid & 31;

    float m = -1e30f;
    for (int i = tid; i < n; i += 1024) m = fmaxf(m, x[i]);
    #pragma unroll
    for (int o = 16; o > 0; o >>= 1) m = fmaxf(m, __shfl_xor_sync(0xffffffff, m, o));
    if (lid == 0) red[wid] = m;
    __syncthreads();
    if (wid == 0) {
        float v = red[lid];
        #pragma unroll
        for (int o = 16; o > 0; o >>= 1) v = fmaxf(v, __shfl_xor_sync(0xffffffff, v, o));
        red[lid] = v;
    }
    __syncthreads();
    m = red[0];

    float s = 0.f;
    for (int i = tid; i < n; i += 1024) s += expf(x[i] - m);
    #pragma unroll
    for (int o = 16; o > 0; o >>= 1) s += __shfl_xor_sync(0xffffffff, s, o);
    __syncthreads();
    if (lid == 0) red[wid] = s;
    __syncthreads();
    if (wid == 0) {
        float v = red[lid];
        #pragma unroll
        for (int o = 16; o > 0; o >>= 1) v += __shfl_xor_sync(0xffffffff, v, o);
        red[lid] = v;
    }
    __syncthreads();
    float lse = m + logf(red[0]);
    for (int i = tid; i < n; i += 1024) y[i] = x[i] - lse;
}

// ---------------- GRU gates -------------------------------------------------
__global__ void gru_gates(const float* __restrict__ gi, const float* __restrict__ gh,
                          const float* __restrict__ h_prev, float* __restrict__ h_new)
{
    int idx = blockIdx.x * blockDim.x + threadIdx.x;
    if (idx >= B * Hd) return;
    int b = idx / Hd, j = idx - b * Hd;
    long base = (long)b * 3 * Hd;
    float ir = gi[base + j],          hr = gh[base + j];
    float iz = gi[base + Hd + j],     hz = gh[base + Hd + j];
    float in_ = gi[base + 2 * Hd + j], hn = gh[base + 2 * Hd + j];
    float r = 1.f / (1.f + expf(-(ir + hr)));
    float z = 1.f / (1.f + expf(-(iz + hz)));
    float nn = tanhf(in_ + r * hn);
    h_new[idx] = (1.f - z) * nn + z * h_prev[idx];
}

// ---------------- launch ----------------------------------------------------
extern "C" void kernel_launch(void* const* d_in, const int* in_sizes, int n_in,
                              void* d_out, int out_size)
{
    const float* embedded = (const float*)d_in[0];   // [1,B,H]
    const float* hidden   = (const float*)d_in[1];   // [1,B,H]
    const float* enc      = (const float*)d_in[2];   // [L,H]
    const float* attn_W   = (const float*)d_in[3];   // [L,2H]
    const float* attn_b   = (const float*)d_in[4];   // [L]
    const float* comb_W   = (const float*)d_in[5];   // [H,2H]
    const float* comb_b   = (const float*)d_in[6];   // [H]
    const float* gru_Wih  = (const float*)d_in[7];   // [3H,H]
    const float* gru_Whh  = (const float*)d_in[8];   // [3H,H]
    const float* gru_bih  = (const float*)d_in[9];   // [3H]
    const float* gru_bhh  = (const float*)d_in[10];  // [3H]
    const float* out_W    = (const float*)d_in[11];  // [V,H]
    const float* out_b    = (const float*)d_in[12];  // [V]

    float* out = (float*)d_out;
    float* out_logp = out + OUT_LOGP;
    float* out_h    = out + OUT_H;
    float* out_aw   = out + OUT_AW;

    float *xh, *scores, *attn, *xa, *o, *gi, *gh, *logits;
    cudaGetSymbolAddress((void**)&xh, g_xh);
    cudaGetSymbolAddress((void**)&scores, g_scores);
    cudaGetSymbolAddress((void**)&attn, g_attn);
    cudaGetSymbolAddress((void**)&xa, g_xa);
    cudaGetSymbolAddress((void**)&o, g_o);
    cudaGetSymbolAddress((void**)&gi, g_gi);
    cudaGetSymbolAddress((void**)&gh, g_gh);
    cudaGetSymbolAddress((void**)&logits, g_logits);

    // 1. xh = concat(x, h)
    concat2<<<(B * 2 * Hd + 255) / 256, 256>>>(embedded, hidden, xh, B, Hd);

    // 2. scores = xh @ attn_W^T + attn_b   [B, L]
    {
        dim3 grid((L + BN - 1) / BN, B / BM);
        gemm_tn<<<grid, 256>>>(xh, attn_W, attn_b, scores, B, L, 2 * Hd, 0);
    }

    // 3. attn_weights = softmax(scores)  -> directly into d_out tail
    softmax_rows<<<B, 128>>>(scores, out_aw, L);

    // 4. attn_applied = attn_weights @ enc   [B, H]
    {
        dim3 grid(Hd / BN, B / BM);
        gemm_nn<<<grid, 256>>>(out_aw, enc, attn, B, Hd, L);
    }

    // 5. xa = concat(x, attn_applied)
    concat2<<<(B * 2 * Hd + 255) / 256, 256>>>(embedded, attn, xa, B, Hd);

    // 6. o = relu(xa @ comb_W^T + comb_b)   [B, H]
    {
        dim3 grid(Hd / BN, B / BM);
        gemm_tn<<<grid, 256>>>(xa, comb_W, comb_b, o, B, Hd, 2 * Hd, 1);
    }

    // 7. gi = o @ Wih^T + bih ; gh = h @ Whh^T + bhh   [B, 3H]
    {
        dim3 grid(3 * Hd / BN, B / BM);
        gemm_tn<<<grid, 256>>>(o, gru_Wih, gru_bih, gi, B, 3 * Hd, Hd, 0);
        gemm_tn<<<grid, 256>>>(hidden, gru_Whh, gru_bhh, gh, B, 3 * Hd, Hd, 0);
    }

    // 8. h_new -> out_h
    gru_gates<<<(B * Hd + 255) / 256, 256>>>(gi, gh, hidden, out_h);

    // 9. logits = h_new @ out_W^T + out_b   [B, V]
    {
        dim3 grid((V + BN - 1) / BN, B / BM);
        gemm_tn<<<grid, 256>>>(out_h, out_W, out_b, logits, B, V, Hd, 0);
    }

    // 10. logp = log_softmax(logits) -> out_logp
    logsoftmax_rows<<<B, 1024>>>(logits, out_logp, V);
}

// round 2
// speedup vs baseline: 2.9395x; 2.9395x over previous
#include <cuda_runtime.h>
#include <math.h>

// Problem constants
#define B   256
#define Hd  1024
#define L   400
#define V   50257

// Output layout: logp [B*V], h_new [B*H], attn_weights [B*L]
#define OUT_H    ((long)B * V)
#define OUT_AW   ((long)B * V + (long)B * Hd)

// ---------------- scratch (device globals) ---------------------------------
__device__ float g_xh[B * 2 * Hd];
__device__ float g_scores[B * L];
__device__ float g_attn[B * Hd];
__device__ float g_xa[B * 2 * Hd];
__device__ float g_o[B * Hd];
__device__ float g_gi[B * 3 * Hd];
__device__ float g_gh[B * 3 * Hd];
__device__ float g_logits[(long)B * V];
__device__ float g_part[8L * B * Hd];   // split-K partials (max 8*256*1024)

// ---------------- tf32 helpers ---------------------------------------------
__device__ __forceinline__ unsigned f2tf(float x) {
    unsigned r;
    asm("cvt.rna.tf32.f32 %0, %1;" : "=r"(r) : "f"(x));
    return r;
}

__device__ __forceinline__ void mma_tf32(float* c, const unsigned* a, const unsigned* b) {
    asm volatile(
        "mma.sync.aligned.m16n8k8.row.col.f32.tf32.tf32.f32 "
        "{%0,%1,%2,%3}, {%4,%5,%6,%7}, {%8,%9}, {%0,%1,%2,%3};"
        : "+f"(c[0]), "+f"(c[1]), "+f"(c[2]), "+f"(c[3])
        : "r"(a[0]), "r"(a[1]), "r"(a[2]), "r"(a[3]), "r"(b[0]), "r"(b[1]));
}

// ---------------- tf32 tensor-core GEMM ------------------------------------
// C[M,N] = A[M,K] @ Bop + (bias)   with optional split-K (blockIdx.z = chunk)
// TRANSB=1: Bop = W[N,K]^T  (W row-major, K contiguous)
// TRANSB=0: Bop = Bm[K,N]   (row-major, N contiguous)
// direct=1: write C with bias(+relu). direct=0: write partials at z*M*N, no bias.
// Block tile 128x128x32, 256 threads, 8 warps (2m x 4n), warp tile 64x32.
template<int TRANSB>
__global__ __launch_bounds__(256, 1) void gemm_tf32(
    const float* __restrict__ A, const float* __restrict__ Bsrc,
    const float* __restrict__ bias, float* __restrict__ C,
    int M, int N, int K, int chunkK, int relu, int direct)
{
    __shared__ unsigned As[128][36];
    __shared__ unsigned Bs[128][36];

    int tid = threadIdx.x;
    int lane = tid & 31;
    int wid = tid >> 5;
    int wm = wid >> 2;        // 0..1
    int wn = wid & 3;         // 0..3
    int g = lane >> 2;        // groupID 0..7
    int q = lane & 3;         // threadID_in_group 0..3

    int m0 = blockIdx.y * 128;
    int n0 = blockIdx.x * 128;
    int kstart = blockIdx.z * chunkK;
    int kend = min(kstart + chunkK, K);

    // loader indices
    int ar = tid >> 3;           // 0..31
    int ac = (tid & 7) * 4;      // 0..28
    // TRANSB=0 loader
    int bn = tid & 127;          // 0..127
    int bk = (tid >> 7) * 16;    // 0 or 16

    float4 ra[4];
    float4 rb[4];
    float  rbn[16];

    float acc[4][4][4];
    #pragma unroll
    for (int i = 0; i < 4; i++)
        #pragma unroll
        for (int j = 0; j < 4; j++)
            #pragma unroll
            for (int v = 0; v < 4; v++) acc[i][j][v] = 0.f;

    auto loadA = [&](int k0) {
        #pragma unroll
        for (int i = 0; i < 4; i++) {
            int m = m0 + ar + 32 * i;
            int k = k0 + ac;
            ra[i] = make_float4(0.f, 0.f, 0.f, 0.f);
            if (k < K) ra[i] = *(const float4*)&A[(long)m * K + k];
        }
    };
    auto storeA = [&]() {
        #pragma unroll
        for (int i = 0; i < 4; i++) {
            uint4 u = make_uint4(f2tf(ra[i].x), f2tf(ra[i].y), f2tf(ra[i].z), f2tf(ra[i].w));
            *(uint4*)&As[ar + 32 * i][ac] = u;
        }
    };
    auto loadB = [&](int k0) {
        if (TRANSB) {
            #pragma unroll
            for (int i = 0; i < 4; i++) {
                int n = n0 + ar + 32 * i;
                int k = k0 + ac;
                rb[i] = make_float4(0.f, 0.f, 0.f, 0.f);
                if (n < N && k < K) rb[i] = *(const float4*)&Bsrc[(long)n * K + k];
            }
        } else {
            #pragma unroll
            for (int j = 0; j < 16; j++) {
                int k = k0 + bk + j;
                int n = n0 + bn;
                rbn[j] = (k < K && n < N) ? Bsrc[(long)k * N + n] : 0.f;
            }
        }
    };
    auto storeB = [&]() {
        if (TRANSB) {
            #pragma unroll
            for (int i = 0; i < 4; i++) {
                uint4 u = make_uint4(f2tf(rb[i].x), f2tf(rb[i].y), f2tf(rb[i].z), f2tf(rb[i].w));
                *(uint4*)&Bs[ar + 32 * i][ac] = u;
            }
        } else {
            #pragma unroll
            for (int j4 = 0; j4 < 4; j4++) {
                uint4 u = make_uint4(f2tf(rbn[j4 * 4 + 0]), f2tf(rbn[j4 * 4 + 1]),
                                     f2tf(rbn[j4 * 4 + 2]), f2tf(rbn[j4 * 4 + 3]));
                *(uint4*)&Bs[bn][bk + j4 * 4] = u;
            }
        }
    };
    auto compute = [&]() {
        #pragma unroll
        for (int ks = 0; ks < 4; ks++) {
            int kc = ks * 8;
            unsigned af[4][4], bf[4][2];
            #pragma unroll
            for (int mt = 0; mt < 4; mt++) {
                int r = wm * 64 + mt * 16 + g;
                af[mt][0] = As[r][kc + q];
                af[mt][1] = As[r + 8][kc + q];
                af[mt][2] = As[r][kc + q + 4];
                af[mt][3] = As[r + 8][kc + q + 4];
            }
            #pragma unroll
            for (int nt = 0; nt < 4; nt++) {
                int n = wn * 32 + nt * 8 + g;
                bf[nt][0] = Bs[n][kc + q];
                bf[nt][1] = Bs[n][kc + q + 4];
            }
            #pragma unroll
            for (int mt = 0; mt < 4; mt++)
                #pragma unroll
                for (int nt = 0; nt < 4; nt++)
                    mma_tf32(acc[mt][nt], af[mt], bf[nt]);
        }
    };

    loadA(kstart); loadB(kstart);
    storeA(); storeB();
    __syncthreads();
    for (int k0 = kstart + 32; k0 < kend; k0 += 32) {
        loadA(k0); loadB(k0);
        compute();
        __syncthreads();
        storeA(); storeB();
        __syncthreads();
    }
    compute();

    // epilogue
    float* Cw = direct ? C : (C + (long)blockIdx.z * M * N);
    #pragma unroll
    for (int mt = 0; mt < 4; mt++) {
        int row = m0 + wm * 64 + mt * 16 + g;
        #pragma unroll
        for (int nt = 0; nt < 4; nt++) {
            int col = n0 + wn * 32 + nt * 8 + 2 * q;
            float v0 = acc[mt][nt][0], v1 = acc[mt][nt][1];
            float v2 = acc[mt][nt][2], v3 = acc[mt][nt][3];
            if (direct) {
                float b0 = (col < N) ? bias[col] : 0.f;
                float b1 = (col + 1 < N) ? bias[col + 1] : 0.f;
                v0 += b0; v1 += b1; v2 += b0; v3 += b1;
                if (relu) {
                    v0 = fmaxf(v0, 0.f); v1 = fmaxf(v1, 0.f);
                    v2 = fmaxf(v2, 0.f); v3 = fmaxf(v3, 0.f);
                }
            }
            if (col < N)     Cw[(long)row * N + col] = v0;
            if (col + 1 < N) Cw[(long)row * N + col + 1] = v1;
            if (col < N)     Cw[(long)(row + 8) * N + col] = v2;
            if (col + 1 < N) Cw[(long)(row + 8) * N + col + 1] = v3;
        }
    }
}

// ---------------- split-K reduce (+bias, +relu) — deterministic ------------
__global__ void reduce_bias(const float* __restrict__ part, const float* __restrict__ bias,
                            float* __restrict__ out, int MN, int N, int SK, int relu)
{
    int idx = blockIdx.x * blockDim.x + threadIdx.x;
    if (idx >= MN) return;
    float s = 0.f;
    for (int c = 0; c < SK; c++) s += part[(long)c * MN + idx];
    if (bias) s += bias[idx % N];
    if (relu) s = fmaxf(s, 0.f);
    out[idx] = s;
}

// ---------------- concat along feature dim ---------------------------------
__global__ void concat2(const float* __restrict__ a, const float* __restrict__ b,
                        float* __restrict__ out, int rows, int h)
{
    int idx = blockIdx.x * blockDim.x + threadIdx.x;
    int total = rows * 2 * h;
    if (idx >= total) return;
    int r = idx / (2 * h);
    int c = idx - r * 2 * h;
    out[idx] = (c < h) ? a[r * h + c] : b[r * h + (c - h)];
}

// ---------------- fast exp (full-rate FFMA path, rel err ~4e-5) ------------
__device__ __forceinline__ float fexp(float x)
{
    float t = fmaxf(x * 1.44269504f, -125.0f);
    float fi = t + 12582912.f;                 // round-to-nearest int
    int   i = __float_as_int(fi);
    float fr = t - (fi - 12582912.f);          // [-0.5, 0.5]
    float y = fr * 0.69314718f;
    float p = fmaf(y, 0.25f, 1.f);
    p = fmaf(y * p, 0.33333333f, 1.f);
    p = fmaf(y * p, 0.5f, 1.f);
    p = fmaf(y, p, 1.f);
    return __int_as_float((i + (127 - 0x4B400000)) << 23) * p;
}

// ---------------- softmax over rows (L=400) --------------------------------
__global__ void softmax_rows(const float* __restrict__ in, float* __restrict__ out, int n)
{
    int row = blockIdx.x;
    const float* x = in + (long)row * n;
    float* y = out + (long)row * n;
    __shared__ float red[4];
    int tid = threadIdx.x;          // 128 threads
    int wid = tid >> 5, lid = tid & 31;

    float m = -1e30f;
    for (int i = tid; i < n; i += 128) m = fmaxf(m, x[i]);
    #pragma unroll
    for (int o = 16; o > 0; o >>= 1) m = fmaxf(m, __shfl_xor_sync(0xffffffff, m, o));
    if (lid == 0) red[wid] = m;
    __syncthreads();
    m = fmaxf(fmaxf(red[0], red[1]), fmaxf(red[2], red[3]));

    float s = 0.f;
    for (int i = tid; i < n; i += 128) s += fexp(x[i] - m);
    #pragma unroll
    for (int o = 16; o > 0; o >>= 1) s += __shfl_xor_sync(0xffffffff, s, o);
    __syncthreads();
    if (lid == 0) red[wid] = s;
    __syncthreads();
    s = red[0] + red[1] + red[2] + red[3];
    float inv = 1.f / s;
    for (int i = tid; i < n; i += 128) y[i] = fexp(x[i] - m) * inv;
}

// ---------------- log_softmax over rows of length V ------------------------
__global__ void logsoftmax_rows(const float* __restrict__ in, float* __restrict__ out, int n)
{
    int row = blockIdx.x;
    const float* x = in + (long)row * n;
    float* y = out + (long)row * n;
    __shared__ float red[32];
    int tid = threadIdx.x;          // 1024 threads
    int wid = tid >> 5, lid = tid & 31;

    float m = -1e30f;
    for (int i = tid; i < n; i += 1024) m = fmaxf(m, x[i]);
    #pragma unroll
    for (int o = 16; o > 0; o >>= 1) m = fmaxf(m, __shfl_xor_sync(0xffffffff, m, o));
    if (lid == 0) red[wid] = m;
    __syncthreads();
    if (wid == 0) {
        float v = red[lid];
        #pragma unroll
        for (int o = 16; o > 0; o >>= 1) v = fmaxf(v, __shfl_xor_sync(0xffffffff, v, o));
        red[lid] = v;
    }
    __syncthreads();
    m = red[0];

    float s = 0.f;
    for (int i = tid; i < n; i += 1024) s += fexp(x[i] - m);
    #pragma unroll
    for (int o = 16; o > 0; o >>= 1) s += __shfl_xor_sync(0xffffffff, s, o);
    __syncthreads();
    if (lid == 0) red[wid] = s;
    __syncthreads();
    if (wid == 0) {
        float v = red[lid];
        #pragma unroll
        for (int o = 16; o > 0; o >>= 1) v += __shfl_xor_sync(0xffffffff, v, o);
        red[lid] = v;
    }
    __syncthreads();
    float lse = m + logf(red[0]);
    for (int i = tid; i < n; i += 1024) y[i] = x[i] - lse;
}

// ---------------- GRU gates -------------------------------------------------
__global__ void gru_gates(const float* __restrict__ gi, const float* __restrict__ gh,
                          const float* __restrict__ h_prev, float* __restrict__ h_new)
{
    int idx = blockIdx.x * blockDim.x + threadIdx.x;
    if (idx >= B * Hd) return;
    int b = idx / Hd, j = idx - b * Hd;
    long base = (long)b * 3 * Hd;
    float ir = gi[base + j],           hr = gh[base + j];
    float iz = gi[base + Hd + j],      hz = gh[base + Hd + j];
    float in_ = gi[base + 2 * Hd + j], hn = gh[base + 2 * Hd + j];
    float r = 1.f / (1.f + expf(-(ir + hr)));
    float z = 1.f / (1.f + expf(-(iz + hz)));
    float nn = tanhf(in_ + r * hn);
    h_new[idx] = (1.f - z) * nn + z * h_prev[idx];
}

// ---------------- launch ----------------------------------------------------
extern "C" void kernel_launch(void* const* d_in, const int* in_sizes, int n_in,
                              void* d_out, int out_size)
{
    const float* embedded = (const float*)d_in[0];
    const float* hidden   = (const float*)d_in[1];
    const float* enc      = (const float*)d_in[2];
    const float* attn_W   = (const float*)d_in[3];
    const float* attn_b   = (const float*)d_in[4];
    const float* comb_W   = (const float*)d_in[5];
    const float* comb_b   = (const float*)d_in[6];
    const float* gru_Wih  = (const float*)d_in[7];
    const float* gru_Whh  = (const float*)d_in[8];
    const float* gru_bih  = (const float*)d_in[9];
    const float* gru_bhh  = (const float*)d_in[10];
    const float* out_W    = (const float*)d_in[11];
    const float* out_b    = (const float*)d_in[12];

    float* out = (float*)d_out;
    float* out_logp = out;
    float* out_h    = out + OUT_H;
    float* out_aw   = out + OUT_AW;

    float *xh, *scores, *attn, *xa, *o, *gi, *gh, *logits, *part;
    cudaGetSymbolAddress((void**)&xh, g_xh);
    cudaGetSymbolAddress((void**)&scores, g_scores);
    cudaGetSymbolAddress((void**)&attn, g_attn);
    cudaGetSymbolAddress((void**)&xa, g_xa);
    cudaGetSymbolAddress((void**)&o, g_o);
    cudaGetSymbolAddress((void**)&gi, g_gi);
    cudaGetSymbolAddress((void**)&gh, g_gh);
    cudaGetSymbolAddress((void**)&logits, g_logits);
    cudaGetSymbolAddress((void**)&part, g_part);

    // 1. xh = concat(x, h)
    concat2<<<(B * 2 * Hd + 255) / 256, 256>>>(embedded, hidden, xh, B, Hd);

    // 2. scores = xh @ attn_W^T + attn_b  [B, L], split-K=8
    gemm_tf32<1><<<dim3(4, 2, 8), 256>>>(xh, attn_W, nullptr, part,
                                         B, L, 2 * Hd, 256, 0, 0);
    reduce_bias<<<(B * L + 255) / 256, 256>>>(part, attn_b, scores, B * L, L, 8, 0);

    // 3. attn_weights = softmax(scores)
    softmax_rows<<<B, 128>>>(scores, out_aw, L);

    // 4. attn_applied = attn_weights @ enc  [B, H], split-K=4
    gemm_tf32<0><<<dim3(8, 2, 4), 256>>>(out_aw, enc, nullptr, part,
                                         B, Hd, L, 128, 0, 0);
    reduce_bias<<<(B * Hd + 255) / 256, 256>>>(part, nullptr, attn, B * Hd, Hd, 4, 0);

    // 5. xa = concat(x, attn_applied)
    concat2<<<(B * 2 * Hd + 255) / 256, 256>>>(embedded, attn, xa, B, Hd);

    // 6. o = relu(xa @ comb_W^T + comb_b), split-K=8
    gemm_tf32<1><<<dim3(8, 2, 8), 256>>>(xa, comb_W, nullptr, part,
                                         B, Hd, 2 * Hd, 256, 0, 0);
    reduce_bias<<<(B * Hd + 255) / 256, 256>>>(part, comb_b, o, B * Hd, Hd, 8, 1);

    // 7. gi / gh, split-K=2 each
    gemm_tf32<1><<<dim3(24, 2, 2), 256>>>(o, gru_Wih, nullptr, part,
                                          B, 3 * Hd, Hd, 512, 0, 0);
    reduce_bias<<<(B * 3 * Hd + 255) / 256, 256>>>(part, gru_bih, gi, B * 3 * Hd, 3 * Hd, 2, 0);
    gemm_tf32<1><<<dim3(24, 2, 2), 256>>>(hidden, gru_Whh, nullptr, part,
                                          B, 3 * Hd, Hd, 512, 0, 0);
    reduce_bias<<<(B * 3 * Hd + 255) / 256, 256>>>(part, gru_bhh, gh, B * 3 * Hd, 3 * Hd, 2, 0);

    // 8. h_new -> out_h
    gru_gates<<<(B * Hd + 255) / 256, 256>>>(gi, gh, hidden, out_h);

    // 9. logits = h_new @ out_W^T + out_b  [B, V], direct
    gemm_tf32<1><<<dim3((V + 127) / 128, 2, 1), 256>>>(out_h, out_W, out_b, logits,
                                                       B, V, Hd, Hd, 0, 1);

    // 10. logp = log_softmax(logits)
    logsoftmax_rows<<<B, 1024>>>(logits, out_logp, V);
}

// round 4
// speedup vs baseline: 4.3613x; 1.4837x over previous
#include <cuda_runtime.h>
#include <cuda_fp16.h>
#include <math.h>
#include <stdint.h>

// Problem constants
#define B   256
#define Hd  1024
#define L   400
#define V   50257

#define OUT_H    ((long)B * V)
#define OUT_AW   ((long)B * V + (long)B * Hd)

// ---------------- scratch (device globals) ---------------------------------
__device__ float g_xh[B * 2 * Hd];
__device__ float g_scores[B * L];
__device__ float g_attn[B * Hd];
__device__ float g_xa[B * 2 * Hd];
__device__ float g_o[B * Hd];
__device__ float g_gi[B * 3 * Hd];
__device__ float g_gh[B * 3 * Hd];
__device__ float g_logits[(long)B * V];
__device__ float g_part[8L * B * Hd];

// ---------------- helpers ---------------------------------------------------
__device__ __forceinline__ uint32_t smem_u32(const void* p) {
    uint32_t a;
    asm("{ .reg .u64 t; cvta.to.shared.u64 t, %1; cvt.u32.u64 %0, t; }" : "=r"(a) : "l"(p));
    return a;
}

__device__ __forceinline__ uint32_t h2bits(float x, float y) {
    __half2 h = __floats2half2_rn(x, y);
    return *(uint32_t*)&h;
}

#define SWZ128(x) ((x) ^ (((x) >> 3) & 0x70))

__device__ __forceinline__ void ldsm_x4(uint32_t* r, uint32_t addr) {
    asm volatile("ldmatrix.sync.aligned.m8n8.x4.shared.b16 {%0,%1,%2,%3}, [%4];"
                 : "=r"(r[0]), "=r"(r[1]), "=r"(r[2]), "=r"(r[3]) : "r"(addr));
}

__device__ __forceinline__ void mma_f16(float* c, const uint32_t* a, const uint32_t* b) {
    asm volatile(
        "mma.sync.aligned.m16n8k16.row.col.f32.f16.f16.f32 "
        "{%0,%1,%2,%3}, {%4,%5,%6,%7}, {%8,%9}, {%0,%1,%2,%3};"
        : "+f"(c[0]), "+f"(c[1]), "+f"(c[2]), "+f"(c[3])
        : "r"(a[0]), "r"(a[1]), "r"(a[2]), "r"(a[3]), "r"(b[0]), "r"(b[1]));
}

// ---------------- fp16 tensor-core GEMM -------------------------------------
// C[M,N] = A[M,K] @ Bop (+bias)
// TRANSB=1: Bop = W[N,K]^T  (row-major W, K contiguous)
// TRANSB=0: Bop = Bm[K,N]   (row-major, N contiguous)
// M = 256 always (grid.y = 2, 128 rows per CTA). Split-K via blockIdx.z.
// Block tile 128x128x64, 256 threads, 8 warps (2m x 4n), warp tile 64x32.
// smem: 2 stages x (A 16KB + B 16KB) = 64KB dynamic, SW128-swizzled 128B rows.
#define GH_SMEM 65536

template<int TRANSB>
__global__ __launch_bounds__(256, 1) void gemm_h16(
    const float* __restrict__ A, const float* __restrict__ Bsrc,
    const float* __restrict__ bias, float* __restrict__ C,
    int M, int N, int K, int chunkK, int relu, int direct)
{
    extern __shared__ char smem[];
    const uint32_t sb = smem_u32(smem);

    const int t = threadIdx.x;
    const int lane = t & 31;
    const int wid = t >> 5;
    const int wm = wid >> 2;       // 0..1
    const int wn = wid & 3;        // 0..3
    const int g = lane >> 2;       // 0..7
    const int q = lane & 3;        // 0..3

    const int m0 = blockIdx.y * 128;
    const int n0 = blockIdx.x * 128;
    const int kstart = blockIdx.z * chunkK;
    const int kend = min(kstart + chunkK, K);

    // loader indices (A and TN-B): 128 rows x 16 float4-cols, 8 per thread
    const int arow = t >> 4;          // 0..15 (+16*i)
    const int acol = (t & 15) * 4;    // float col 0..60

    float4 ra[8], rb[8];
    // NN loader staging
    float4 rba[4], rbb[4];

    float acc[4][4][4];
    #pragma unroll
    for (int i = 0; i < 4; i++)
        #pragma unroll
        for (int j = 0; j < 4; j++)
            #pragma unroll
            for (int v = 0; v < 4; v++) acc[i][j][v] = 0.f;

    auto loadA = [&](int k0) {
        #pragma unroll
        for (int i = 0; i < 8; i++) {
            int m = m0 + arow + 16 * i;
            int k = k0 + acol;
            ra[i] = make_float4(0.f, 0.f, 0.f, 0.f);
            if (k < kend) ra[i] = *(const float4*)&A[(long)m * K + k];
        }
    };
    auto loadB = [&](int k0) {
        if (TRANSB) {
            #pragma unroll
            for (int i = 0; i < 8; i++) {
                int n = n0 + arow + 16 * i;
                int k = k0 + acol;
                rb[i] = make_float4(0.f, 0.f, 0.f, 0.f);
                if (n < N && k < kend) rb[i] = *(const float4*)&Bsrc[(long)n * K + k];
            }
        } else {
            #pragma unroll
            for (int i = 0; i < 4; i++) {
                int cell = t + i * 256;
                int kp = cell >> 5;         // 0..31
                int nq = cell & 31;         // 0..31
                int k = k0 + 2 * kp;
                int n = n0 + nq * 4;
                rba[i] = make_float4(0.f, 0.f, 0.f, 0.f);
                rbb[i] = make_float4(0.f, 0.f, 0.f, 0.f);
                if (k < kend && n < N) {
                    rba[i] = *(const float4*)&Bsrc[(long)k * N + n];
                    rbb[i] = *(const float4*)&Bsrc[(long)(k + 1) * N + n];
                }
            }
        }
    };
    auto storeAB = [&](int s) {
        char* Ab = smem + s * 32768;
        char* Bb = smem + s * 32768 + 16384;
        #pragma unroll
        for (int i = 0; i < 8; i++) {
            int row = arow + 16 * i;
            uint32_t off = SWZ128((uint32_t)(row * 128 + acol * 2));
            *(uint2*)(Ab + off) = make_uint2(h2bits(ra[i].x, ra[i].y), h2bits(ra[i].z, ra[i].w));
        }
        if (TRANSB) {
            #pragma unroll
            for (int i = 0; i < 8; i++) {
                int row = arow + 16 * i;
                uint32_t off = SWZ128((uint32_t)(row * 128 + acol * 2));
                *(uint2*)(Bb + off) = make_uint2(h2bits(rb[i].x, rb[i].y), h2bits(rb[i].z, rb[i].w));
            }
        } else {
            #pragma unroll
            for (int i = 0; i < 4; i++) {
                int cell = t + i * 256;
                int kp = cell >> 5;
                int nq = cell & 31;
                const float* fa = (const float*)&rba[i];
                const float* fb = (const float*)&rbb[i];
                #pragma unroll
                for (int j = 0; j < 4; j++) {
                    int row = nq * 4 + j;
                    uint32_t off = SWZ128((uint32_t)(row * 128 + kp * 4));
                    *(uint32_t*)(Bb + off) = h2bits(fa[j], fb[j]);
                }
            }
        }
    };

    const int a_row = lane & 15;
    const int a_cb = (lane >> 4) << 4;
    const int b_row = (lane & 7) + ((lane >> 4) << 3);
    const int b_cb = ((lane >> 3) & 1) << 4;

    auto compute = [&](int s) {
        const uint32_t Ab = sb + s * 32768;
        const uint32_t Bb = Ab + 16384;
        #pragma unroll
        for (int ks = 0; ks < 4; ks++) {
            uint32_t af[4][4], bf[2][4];
            #pragma unroll
            for (int mt = 0; mt < 4; mt++) {
                int r = wm * 64 + mt * 16 + a_row;
                ldsm_x4(af[mt], Ab + SWZ128((uint32_t)(r * 128 + ks * 32 + a_cb)));
            }
            #pragma unroll
            for (int np = 0; np < 2; np++) {
                int r = wn * 32 + np * 16 + b_row;
                ldsm_x4(bf[np], Bb + SWZ128((uint32_t)(r * 128 + ks * 32 + b_cb)));
            }
            #pragma unroll
            for (int mt = 0; mt < 4; mt++)
                #pragma unroll
                for (int nt = 0; nt < 4; nt++)
                    mma_f16(acc[mt][nt], af[mt], &bf[nt >> 1][(nt & 1) * 2]);
        }
    };

    const int ntiles = (kend - kstart + 63) / 64;

    loadA(kstart); loadB(kstart);
    storeAB(0);
    __syncthreads();
    for (int c = 1; c < ntiles; c++) {
        loadA(kstart + c * 64); loadB(kstart + c * 64);
        compute((c - 1) & 1);
        __syncthreads();
        storeAB(c & 1);
        __syncthreads();
    }
    compute((ntiles - 1) & 1);

    // epilogue
    float* Cw = direct ? C : (C + (long)blockIdx.z * M * N);
    #pragma unroll
    for (int mt = 0; mt < 4; mt++) {
        int row = m0 + wm * 64 + mt * 16 + g;
        #pragma unroll
        for (int nt = 0; nt < 4; nt++) {
            int col = n0 + wn * 32 + nt * 8 + 2 * q;
            float v0 = acc[mt][nt][0], v1 = acc[mt][nt][1];
            float v2 = acc[mt][nt][2], v3 = acc[mt][nt][3];
            if (direct) {
                float b0 = (col < N) ? bias[col] : 0.f;
                float b1 = (col + 1 < N) ? bias[col + 1] : 0.f;
                v0 += b0; v1 += b1; v2 += b0; v3 += b1;
                if (relu) {
                    v0 = fmaxf(v0, 0.f); v1 = fmaxf(v1, 0.f);
                    v2 = fmaxf(v2, 0.f); v3 = fmaxf(v3, 0.f);
                }
            }
            if (col < N)     Cw[(long)row * N + col] = v0;
            if (col + 1 < N) Cw[(long)row * N + col + 1] = v1;
            if (col < N)     Cw[(long)(row + 8) * N + col] = v2;
            if (col + 1 < N) Cw[(long)(row + 8) * N + col + 1] = v3;
        }
    }
}

// ---------------- split-K reduce (+bias, +relu) — deterministic -------------
__global__ void reduce_bias(const float* __restrict__ part, const float* __restrict__ bias,
                            float* __restrict__ out, int MN, int N, int SK, int relu)
{
    int idx = blockIdx.x * blockDim.x + threadIdx.x;
    if (idx >= MN) return;
    float s = 0.f;
    for (int c = 0; c < SK; c++) s += part[(long)c * MN + idx];
    if (bias) s += bias[idx % N];
    if (relu) s = fmaxf(s, 0.f);
    out[idx] = s;
}

// ---------------- concat along feature dim -----------------------------------
__global__ void concat2(const float* __restrict__ a, const float* __restrict__ b,
                        float* __restrict__ out, int rows, int h)
{
    int idx = blockIdx.x * blockDim.x + threadIdx.x;
    int total = rows * 2 * h;
    if (idx >= total) return;
    int r = idx / (2 * h);
    int c = idx - r * 2 * h;
    out[idx] = (c < h) ? a[r * h + c] : b[r * h + (c - h)];
}

// ---------------- fast exp ---------------------------------------------------
__device__ __forceinline__ float fexp(float x)
{
    float t = fmaxf(x * 1.44269504f, -125.0f);
    float fi = t + 12582912.f;
    int   i = __float_as_int(fi);
    float fr = t - (fi - 12582912.f);
    float y = fr * 0.69314718f;
    float p = fmaf(y, 0.25f, 1.f);
    p = fmaf(y * p, 0.33333333f, 1.f);
    p = fmaf(y * p, 0.5f, 1.f);
    p = fmaf(y, p, 1.f);
    return __int_as_float((i + (127 - 0x4B400000)) << 23) * p;
}

// ---------------- softmax over rows (L=400) ----------------------------------
__global__ void softmax_rows(const float* __restrict__ in, float* __restrict__ out, int n)
{
    int row = blockIdx.x;
    const float* x = in + (long)row * n;
    float* y = out + (long)row * n;
    __shared__ float red[4];
    int tid = threadIdx.x;
    int wid = tid >> 5, lid = tid & 31;

    float m = -1e30f;
    for (int i = tid; i < n; i += 128) m = fmaxf(m, x[i]);
    #pragma unroll
    for (int o = 16; o > 0; o >>= 1) m = fmaxf(m, __shfl_xor_sync(0xffffffff, m, o));
    if (lid == 0) red[wid] = m;
    __syncthreads();
    m = fmaxf(fmaxf(red[0], red[1]), fmaxf(red[2], red[3]));

    float s = 0.f;
    for (int i = tid; i < n; i += 128) s += fexp(x[i] - m);
    #pragma unroll
    for (int o = 16; o > 0; o >>= 1) s += __shfl_xor_sync(0xffffffff, s, o);
    __syncthreads();
    if (lid == 0) red[wid] = s;
    __syncthreads();
    s = red[0] + red[1] + red[2] + red[3];
    float inv = 1.f / s;
    for (int i = tid; i < n; i += 128) y[i] = fexp(x[i] - m) * inv;
}

// ---------------- log_softmax over rows of length V --------------------------
__global__ void logsoftmax_rows(const float* __restrict__ in, float* __restrict__ out, int n)
{
    int row = blockIdx.x;
    const float* x = in + (long)row * n;
    float* y = out + (long)row * n;
    __shared__ float red[32];
    int tid = threadIdx.x;
    int wid = tid >> 5, lid = tid & 31;

    float m = -1e30f;
    for (int i = tid; i < n; i += 1024) m = fmaxf(m, x[i]);
    #pragma unroll
    for (int o = 16; o > 0; o >>= 1) m = fmaxf(m, __shfl_xor_sync(0xffffffff, m, o));
    if (lid == 0) red[wid] = m;
    __syncthreads();
    if (wid == 0) {
        float v = red[lid];
        #pragma unroll
        for (int o = 16; o > 0; o >>= 1) v = fmaxf(v, __shfl_xor_sync(0xffffffff, v, o));
        red[lid] = v;
    }
    __syncthreads();
    m = red[0];

    float s = 0.f;
    for (int i = tid; i < n; i += 1024) s += fexp(x[i] - m);
    #pragma unroll
    for (int o = 16; o > 0; o >>= 1) s += __shfl_xor_sync(0xffffffff, s, o);
    __syncthreads();
    if (lid == 0) red[wid] = s;
    __syncthreads();
    if (wid == 0) {
        float v = red[lid];
        #pragma unroll
        for (int o = 16; o > 0; o >>= 1) v += __shfl_xor_sync(0xffffffff, v, o);
        red[lid] = v;
    }
    __syncthreads();
    float lse = m + logf(red[0]);
    for (int i = tid; i < n; i += 1024) y[i] = x[i] - lse;
}

// ---------------- GRU gates --------------------------------------------------
__global__ void gru_gates(const float* __restrict__ gi, const float* __restrict__ gh,
                          const float* __restrict__ h_prev, float* __restrict__ h_new)
{
    int idx = blockIdx.x * blockDim.x + threadIdx.x;
    if (idx >= B * Hd) return;
    int b = idx / Hd, j = idx - b * Hd;
    long base = (long)b * 3 * Hd;
    float ir = gi[base + j],           hr = gh[base + j];
    float iz = gi[base + Hd + j],      hz = gh[base + Hd + j];
    float in_ = gi[base + 2 * Hd + j], hn = gh[base + 2 * Hd + j];
    float r = 1.f / (1.f + expf(-(ir + hr)));
    float z = 1.f / (1.f + expf(-(iz + hz)));
    float nn = tanhf(in_ + r * hn);
    h_new[idx] = (1.f - z) * nn + z * h_prev[idx];
}

// ---------------- launch -----------------------------------------------------
extern "C" void kernel_launch(void* const* d_in, const int* in_sizes, int n_in,
                              void* d_out, int out_size)
{
    const float* embedded = (const float*)d_in[0];
    const float* hidden   = (const float*)d_in[1];
    const float* enc      = (const float*)d_in[2];
    const float* attn_W   = (const float*)d_in[3];
    const float* attn_b   = (const float*)d_in[4];
    const float* comb_W   = (const float*)d_in[5];
    const float* comb_b   = (const float*)d_in[6];
    const float* gru_Wih  = (const float*)d_in[7];
    const float* gru_Whh  = (const float*)d_in[8];
    const float* gru_bih  = (const float*)d_in[9];
    const float* gru_bhh  = (const float*)d_in[10];
    const float* out_W    = (const float*)d_in[11];
    const float* out_b    = (const float*)d_in[12];

    float* out = (float*)d_out;
    float* out_logp = out;
    float* out_h    = out + OUT_H;
    float* out_aw   = out + OUT_AW;

    float *xh, *scores, *attn, *xa, *o, *gi, *gh, *logits, *part;
    cudaGetSymbolAddress((void**)&xh, g_xh);
    cudaGetSymbolAddress((void**)&scores, g_scores);
    cudaGetSymbolAddress((void**)&attn, g_attn);
    cudaGetSymbolAddress((void**)&xa, g_xa);
    cudaGetSymbolAddress((void**)&o, g_o);
    cudaGetSymbolAddress((void**)&gi, g_gi);
    cudaGetSymbolAddress((void**)&gh, g_gh);
    cudaGetSymbolAddress((void**)&logits, g_logits);
    cudaGetSymbolAddress((void**)&part, g_part);

    cudaFuncSetAttribute(gemm_h16<1>, cudaFuncAttributeMaxDynamicSharedMemorySize, GH_SMEM);
    cudaFuncSetAttribute(gemm_h16<0>, cudaFuncAttributeMaxDynamicSharedMemorySize, GH_SMEM);

    // 1. xh = concat(x, h)
    concat2<<<(B * 2 * Hd + 255) / 256, 256>>>(embedded, hidden, xh, B, Hd);

    // 2. scores = xh @ attn_W^T + attn_b  [B, L], split-K=8
    gemm_h16<1><<<dim3(4, 2, 8), 256, GH_SMEM>>>(xh, attn_W, nullptr, part,
                                                 B, L, 2 * Hd, 256, 0, 0);
    reduce_bias<<<(B * L + 255) / 256, 256>>>(part, attn_b, scores, B * L, L, 8, 0);

    // 3. attn_weights = softmax(scores)
    softmax_rows<<<B, 128>>>(scores, out_aw, L);

    // 4. attn_applied = attn_weights @ enc  [B, H], split-K=4 (NN)
    gemm_h16<0><<<dim3(8, 2, 4), 256, GH_SMEM>>>(out_aw, enc, nullptr, part,
                                                 B, Hd, L, 128, 0, 0);
    reduce_bias<<<(B * Hd + 255) / 256, 256>>>(part, nullptr, attn, B * Hd, Hd, 4, 0);

    // 5. xa = concat(x, attn_applied)
    concat2<<<(B * 2 * Hd + 255) / 256, 256>>>(embedded, attn, xa, B, Hd);

    // 6. o = relu(xa @ comb_W^T + comb_b), split-K=4
    gemm_h16<1><<<dim3(8, 2, 4), 256, GH_SMEM>>>(xa, comb_W, nullptr, part,
                                                 B, Hd, 2 * Hd, 512, 0, 0);
    reduce_bias<<<(B * Hd + 255) / 256, 256>>>(part, comb_b, o, B * Hd, Hd, 4, 1);

    // 7. gi / gh, split-K=2 each
    gemm_h16<1><<<dim3(24, 2, 2), 256, GH_SMEM>>>(o, gru_Wih, nullptr, part,
                                                  B, 3 * Hd, Hd, 512, 0, 0);
    reduce_bias<<<(B * 3 * Hd + 255) / 256, 256>>>(part, gru_bih, gi, B * 3 * Hd, 3 * Hd, 2, 0);
    gemm_h16<1><<<dim3(24, 2, 2), 256, GH_SMEM>>>(hidden, gru_Whh, nullptr, part,
                                                  B, 3 * Hd, Hd, 512, 0, 0);
    reduce_bias<<<(B * 3 * Hd + 255) / 256, 256>>>(part, gru_bhh, gh, B * 3 * Hd, 3 * Hd, 2, 0);

    // 8. h_new -> out_h
    gru_gates<<<(B * Hd + 255) / 256, 256>>>(gi, gh, hidden, out_h);

    // 9. logits = h_new @ out_W^T + out_b  [B, V], direct
    gemm_h16<1><<<dim3((V + 127) / 128, 2, 1), 256, GH_SMEM>>>(out_h, out_W, out_b, logits,
                                                               B, V, Hd, Hd, 0, 1);

    // 10. logp = log_softmax(logits)
    logsoftmax_rows<<<B, 1024>>>(logits, out_logp, V);
}